// round 15
// baseline (speedup 1.0000x reference)
#include <cuda_runtime.h>
#include <cuda_bf16.h>
#include <cstdint>

#define NV 100000
#define NTOT 200000
#define CLUSTERS 2048
#define GAMMA 1.0f
#define NEG_SLOPE 0.2f

// ---------------- scratch (device globals; no allocation allowed) ----------
// per node: Qhi(64) Qlo(64) Khi(64) Klo(64) Vhi(64) Vlo(64) bf16 = 768 B
__device__ __align__(16) __nv_bfloat16 g_QKV[(size_t)NTOT * 384];
__device__ __align__(16) float g_acc[(size_t)NTOT * 64];
__device__ __align__(16) float g_cnt[NTOT];
// pre-split weights: 4 mats x [hi 64x144B | lo 64x144B] = 4 x 18432 B
__device__ __align__(16) char g_Wpre[73728];

// split float pair into (hi, lo) bf16x2 words; lower half = first element
__device__ __forceinline__ void bf2split(float a, float b, uint32_t& hi, uint32_t& lo) {
    __nv_bfloat162 h = __floats2bfloat162_rn(a, b);
    float ha = __bfloat162float(__low2bfloat16(h));
    float hb = __bfloat162float(__high2bfloat16(h));
    __nv_bfloat162 l = __floats2bfloat162_rn(a - ha, b - hb);
    hi = *reinterpret_cast<uint32_t*>(&h);
    lo = *reinterpret_cast<uint32_t*>(&l);
}

__device__ __forceinline__ void mma16816(float* c, uint32_t a0, uint32_t a1,
                                         uint32_t a2, uint32_t a3,
                                         uint32_t b0, uint32_t b1) {
    asm volatile(
        "mma.sync.aligned.m16n8k16.row.col.f32.bf16.bf16.f32 "
        "{%0,%1,%2,%3}, {%4,%5,%6,%7}, {%8,%9}, {%0,%1,%2,%3};"
        : "+f"(c[0]), "+f"(c[1]), "+f"(c[2]), "+f"(c[3])
        : "r"(a0), "r"(a1), "r"(a2), "r"(a3), "r"(b0), "r"(b1));
}

__device__ __forceinline__ uint32_t smem_u32(const void* p) {
    uint32_t a;
    asm("{ .reg .u64 t; cvta.to.shared.u64 t, %1; cvt.u32.u64 %0, t; }"
        : "=r"(a) : "l"(p));
    return a;
}

#define LDM_X4(r0_, r1_, r2_, r3_, addr) \
    asm volatile("ldmatrix.sync.aligned.m8n8.x4.shared.b16 {%0,%1,%2,%3}, [%4];" \
        : "=r"(r0_), "=r"(r1_), "=r"(r2_), "=r"(r3_) : "r"(addr))
#define LDM_X4T(r0_, r1_, r2_, r3_, addr) \
    asm volatile("ldmatrix.sync.aligned.m8n8.x4.trans.shared.b16 {%0,%1,%2,%3}, [%4];" \
        : "=r"(r0_), "=r"(r1_), "=r"(r2_), "=r"(r3_) : "r"(addr))

#define CP_ASYNC16(dst, src) \
    asm volatile("cp.async.cg.shared.global [%0], [%1], 16;" \
        :: "r"((uint32_t)(dst)), "l"(src) : "memory")
#define CP_COMMIT() asm volatile("cp.async.commit_group;" ::: "memory")
#define CP_WAIT0()  asm volatile("cp.async.wait_group 0;" ::: "memory")
#define CP_WAIT1()  asm volatile("cp.async.wait_group 1;" ::: "memory")

// ---------------- weight prep: split once into g_Wpre ----------------------
__global__ void __launch_bounds__(256) wprep_kernel(
    const float* __restrict__ WQ, const float* __restrict__ WK,
    const float* __restrict__ WV, const float* __restrict__ Wout)
{
    const float* Wsrc[4] = {WQ, WK, WV, Wout};
    int idx = blockIdx.x * 256 + threadIdx.x;     // 512 units total
    if (idx >= 512) return;
    int mat = idx >> 7;
    int rh  = idx & 127;
    int j = rh >> 1, h32 = (rh & 1) * 32;
    const float* w = Wsrc[mat] + j * 64 + h32;
    char* bhi = g_Wpre + mat * 18432 + j * 144 + h32 * 2;
    char* blo = bhi + 9216;
    #pragma unroll
    for (int i = 0; i < 8; ++i) {
        float4 f = *(const float4*)(w + i * 4);
        uint32_t h0, l0, h1, l1;
        bf2split(f.x, f.y, h0, l0);
        bf2split(f.z, f.w, h1, l1);
        *(uint2*)(bhi + i * 8) = make_uint2(h0, h1);
        *(uint2*)(blo + i * 8) = make_uint2(l0, l1);
    }
}

// ---------------- QKV via HMMA (fused 3-product mainloop) ------------------
#define QKV_XHI 0
#define QKV_XLO 18432
#define QKV_W   36864
#define QKV_SMEM 92160

__global__ void __launch_bounds__(256, 2) qkv_kernel(
    const float* __restrict__ xv, const float* __restrict__ xc)
{
    extern __shared__ char sm[];
    const int tid = threadIdx.x;
    const int wid = tid >> 5, lane = tid & 31;
    const int g = lane >> 2, t = lane & 3;
    const int m0 = wid * 16;
    const int r0 = blockIdx.x * 128;
    const uint32_t smu = smem_u32(sm);

    // ---- async copy of pre-split weights (55296 B) ----
    for (int idx = tid; idx < 3456; idx += 256) {
        CP_ASYNC16(smu + QKV_W + idx * 16, (const char*)g_Wpre + idx * 16);
    }
    CP_COMMIT();

    // ---- issue x-row loads early (MLP over the zero phase) ----
    const int xrow = tid >> 1, xh32 = (tid & 1) * 32;
    const int xgr = r0 + xrow;
    const bool xvalid = (xgr < NTOT);
    float4 xf[8];
    if (xvalid) {
        const float* src = (xgr < NV) ? xv + (size_t)xgr * 64 + xh32
                                      : xc + (size_t)(xgr - NV) * 64 + xh32;
        #pragma unroll
        for (int i = 0; i < 8; ++i) xf[i] = *(const float4*)(src + i * 4);
    }

    // ---- fused zero of g_acc / g_cnt ----
    {
        const size_t f4base = (size_t)r0 * 16;
        #pragma unroll
        for (int i = 0; i < 8; ++i) {
            size_t idx = f4base + tid + i * 256;
            if (idx < (size_t)NTOT * 16)
                ((float4*)g_acc)[idx] = make_float4(0.f, 0.f, 0.f, 0.f);
        }
        if (tid < 128 && r0 + tid < NTOT) g_cnt[r0 + tid] = 0.f;
    }

    // ---- convert + store x rows ----
    {
        char* xhi = sm + QKV_XHI + xrow * 144 + xh32 * 2;
        char* xlo = sm + QKV_XLO + xrow * 144 + xh32 * 2;
        if (xvalid) {
            #pragma unroll
            for (int i = 0; i < 8; ++i) {
                uint32_t h0, l0, h1, l1;
                bf2split(xf[i].x, xf[i].y, h0, l0);
                bf2split(xf[i].z, xf[i].w, h1, l1);
                *(uint2*)(xhi + i * 8) = make_uint2(h0, h1);
                *(uint2*)(xlo + i * 8) = make_uint2(l0, l1);
            }
        } else {
            #pragma unroll
            for (int i = 0; i < 8; ++i) {
                *(uint64_t*)(xhi + i * 8) = 0ull;
                *(uint64_t*)(xlo + i * 8) = 0ull;
            }
        }
    }
    CP_WAIT0();
    __syncthreads();

    const int lrow = lane & 7;
    const uint32_t xfrag = smu +
        (uint32_t)(m0 + ((lane >> 3) & 1) * 8 + lrow) * 144 + (uint32_t)((lane >> 4) * 16);
    const uint32_t wfrag = smu + QKV_W +
        (uint32_t)((lane >> 4) * 8 + lrow) * 144 + (uint32_t)(((lane >> 3) & 1) * 16);

    const int rA = r0 + m0 + g;
    const int rB = rA + 8;

    #pragma unroll 1
    for (int mat = 0; mat < 3; ++mat) {
        float c[8][4];
        #pragma unroll
        for (int n = 0; n < 8; ++n)
            #pragma unroll
            for (int j = 0; j < 4; ++j) c[n][j] = 0.f;

        const uint32_t wb = wfrag + (uint32_t)mat * 18432;
        #pragma unroll
        for (int kc = 0; kc < 4; ++kc) {
            uint32_t xh0, xh1, xh2, xh3, xl0, xl1, xl2, xl3;
            LDM_X4(xh0, xh1, xh2, xh3, xfrag + kc * 32);
            LDM_X4(xl0, xl1, xl2, xl3, xfrag + QKV_XLO + kc * 32);
            #pragma unroll
            for (int nb = 0; nb < 4; ++nb) {
                uint32_t wh0, wh1, wh2, wh3, wl0, wl1, wl2, wl3;
                LDM_X4(wh0, wh1, wh2, wh3, wb + (uint32_t)nb * 2304 + kc * 32);
                LDM_X4(wl0, wl1, wl2, wl3, wb + 9216u + (uint32_t)nb * 2304 + kc * 32);
                mma16816(c[2 * nb],     xh0, xh1, xh2, xh3, wh0, wh1);
                mma16816(c[2 * nb + 1], xh0, xh1, xh2, xh3, wh2, wh3);
                mma16816(c[2 * nb],     xh0, xh1, xh2, xh3, wl0, wl1);
                mma16816(c[2 * nb + 1], xh0, xh1, xh2, xh3, wl2, wl3);
                mma16816(c[2 * nb],     xl0, xl1, xl2, xl3, wh0, wh1);
                mma16816(c[2 * nb + 1], xl0, xl1, xl2, xl3, wh2, wh3);
            }
        }

        if (rA < NTOT) {
            #pragma unroll
            for (int nn = 0; nn < 8; ++nn) {
                uint32_t hi, lo;
                bf2split(c[nn][0], c[nn][1], hi, lo);
                size_t off = (size_t)rA * 384 + mat * 128 + 8 * nn + 2 * t;
                *(uint32_t*)(g_QKV + off)      = hi;
                *(uint32_t*)(g_QKV + off + 64) = lo;
            }
        }
        if (rB < NTOT) {
            #pragma unroll
            for (int nn = 0; nn < 8; ++nn) {
                uint32_t hi, lo;
                bf2split(c[nn][2], c[nn][3], hi, lo);
                size_t off = (size_t)rB * 384 + mat * 128 + 8 * nn + 2 * t;
                *(uint32_t*)(g_QKV + off)      = hi;
                *(uint32_t*)(g_QKV + off + 64) = lo;
            }
        }
    }
}

// ---------------- HMMA attention (fused passes, two-group gather) ----------
// smem: 3 tensors (Q, K, V), each [128 rows][272 B]: hi 128B | lo 128B | 16B pad
#define SQ 0
#define SK 34816
#define SV 69632
#define ATTN_SMEM_BYTES 104448

__global__ void __launch_bounds__(256) attn_kernel(
    const int* __restrict__ cvi, const int* __restrict__ cci,
    const float* __restrict__ sat, const int* __restrict__ active_heads,
    const float* __restrict__ head_weights)
{
    extern __shared__ char smc[];
    __shared__ int   sNode[128];
    __shared__ float sBias[128];
    __shared__ float sHw;

    const int tid  = threadIdx.x;
    const int wid  = tid >> 5;
    const int lane = tid & 31;
    const int c    = blockIdx.x;
    const int g    = lane >> 2;
    const int t    = lane & 3;
    const int m0   = wid * 16;
    const uint32_t smu = smem_u32(smc);

    if (tid < 64) {
        sNode[tid] = cvi[c * 64 + tid];
        sBias[tid] = 0.f;
    } else if (tid < 128) {
        int id = cci[c * 64 + tid - 64];
        sNode[tid] = NV + id;
        sBias[tid] = GAMMA * sat[id];
    }
    if (tid == 128) {
        int ah = active_heads[0];
        if (ah < 1) ah = 1;
        if (ah > 4) ah = 4;
        float s = 0.f;
        for (int h = 0; h < 4; ++h) if (h < ah) s += head_weights[h];
        sHw = s / (float)ah;
    }
    __syncthreads();

    // ---- gather via cp.async, two groups: [Q,K] then [V] ----
    {
        const int row = tid >> 1;
        const int h   = tid & 1;
        const int node = sNode[row];
        const char* src = (const char*)g_QKV + (size_t)node * 768;
        // group A: bytes 0..511 (Q hi/lo, K hi/lo)
        #pragma unroll
        for (int i = 0; i < 16; ++i) {
            int gb = (i * 2 + h) * 16;        // 0..496
            int part = gb >> 7;               // 0..3
            int tau = part >> 1;              // 0=Q,1=K
            int which = part & 1;
            int within = gb & 127;
            CP_ASYNC16(smu + tau * 34816 + row * 272 + which * 128 + within,
                       src + gb);
        }
        CP_COMMIT();
        // group B: bytes 512..767 (V hi/lo)
        #pragma unroll
        for (int i = 16; i < 24; ++i) {
            int gb = (i * 2 + h) * 16;        // 512..752
            int which = (gb >> 7) & 1;
            int within = gb & 127;
            CP_ASYNC16(smu + SV + row * 272 + which * 128 + within,
                       src + gb);
        }
        CP_COMMIT();
    }
    CP_WAIT1();        // Q,K resident; V still in flight
    __syncthreads();

    const int lrow = lane & 7;
    const uint32_t qfrag = smu + SQ +
        (uint32_t)(m0 + ((lane >> 3) & 1) * 8 + lrow) * 272 + (uint32_t)((lane >> 4) * 16);
    const uint32_t kfrag = smu + SK +
        (uint32_t)((lane >> 4) * 8 + lrow) * 272 + (uint32_t)(((lane >> 3) & 1) * 16);
    const uint32_t vfrag = smu + SV +
        (uint32_t)(((lane >> 3) & 1) * 8 + lrow) * 272 + (uint32_t)((lane >> 4) * 16);

    // ---- S = Q K^T, fused 3-product HMMA loop ----
    float cS[16][4];
    #pragma unroll
    for (int n = 0; n < 16; ++n)
        #pragma unroll
        for (int j = 0; j < 4; ++j) cS[n][j] = 0.f;

    #pragma unroll
    for (int kc = 0; kc < 4; ++kc) {
        uint32_t qh0, qh1, qh2, qh3, ql0, ql1, ql2, ql3;
        LDM_X4(qh0, qh1, qh2, qh3, qfrag + kc * 32);
        LDM_X4(ql0, ql1, ql2, ql3, qfrag + 128 + kc * 32);
        #pragma unroll
        for (int nb = 0; nb < 8; ++nb) {
            uint32_t kh0, kh1, kh2, kh3, kl0, kl1, kl2, kl3;
            uint32_t ka = kfrag + (uint32_t)nb * (16 * 272) + kc * 32;
            LDM_X4(kh0, kh1, kh2, kh3, ka);
            LDM_X4(kl0, kl1, kl2, kl3, ka + 128);
            mma16816(cS[2 * nb],     qh0, qh1, qh2, qh3, kh0, kh1);
            mma16816(cS[2 * nb + 1], qh0, qh1, qh2, qh3, kh2, kh3);
            mma16816(cS[2 * nb],     qh0, qh1, qh2, qh3, kl0, kl1);
            mma16816(cS[2 * nb + 1], qh0, qh1, qh2, qh3, kl2, kl3);
            mma16816(cS[2 * nb],     ql0, ql1, ql2, ql3, kh0, kh1);
            mma16816(cS[2 * nb + 1], ql0, ql1, ql2, ql3, kh2, kh3);
        }
    }

    // ---- bias + leaky + softmax (register-resident) ----
    float mA = -1e30f, mB = -1e30f;
    #pragma unroll
    for (int n = 0; n < 16; ++n) {
        float b0v = sBias[8 * n + 2 * t];
        float b1v = sBias[8 * n + 2 * t + 1];
        float s;
        s = cS[n][0] * 0.125f + b0v; s = (s > 0.f) ? s : NEG_SLOPE * s; cS[n][0] = s; mA = fmaxf(mA, s);
        s = cS[n][1] * 0.125f + b1v; s = (s > 0.f) ? s : NEG_SLOPE * s; cS[n][1] = s; mA = fmaxf(mA, s);
        s = cS[n][2] * 0.125f + b0v; s = (s > 0.f) ? s : NEG_SLOPE * s; cS[n][2] = s; mB = fmaxf(mB, s);
        s = cS[n][3] * 0.125f + b1v; s = (s > 0.f) ? s : NEG_SLOPE * s; cS[n][3] = s; mB = fmaxf(mB, s);
    }
    mA = fmaxf(mA, __shfl_xor_sync(0xffffffffu, mA, 1));
    mA = fmaxf(mA, __shfl_xor_sync(0xffffffffu, mA, 2));
    mB = fmaxf(mB, __shfl_xor_sync(0xffffffffu, mB, 1));
    mB = fmaxf(mB, __shfl_xor_sync(0xffffffffu, mB, 2));

    float sA = 0.f, sB = 0.f;
    #pragma unroll
    for (int n = 0; n < 16; ++n) {
        cS[n][0] = __expf(cS[n][0] - mA); sA += cS[n][0];
        cS[n][1] = __expf(cS[n][1] - mA); sA += cS[n][1];
        cS[n][2] = __expf(cS[n][2] - mB); sB += cS[n][2];
        cS[n][3] = __expf(cS[n][3] - mB); sB += cS[n][3];
    }
    sA += __shfl_xor_sync(0xffffffffu, sA, 1);
    sA += __shfl_xor_sync(0xffffffffu, sA, 2);
    sB += __shfl_xor_sync(0xffffffffu, sB, 1);
    sB += __shfl_xor_sync(0xffffffffu, sB, 2);

    const float hw = sHw;
    const float scA = hw / sA;
    const float scB = hw / sB;

    uint32_t phi[16][2], plo[16][2];
    #pragma unroll
    for (int n = 0; n < 16; ++n) {
        bf2split(cS[n][0] * scA, cS[n][1] * scA, phi[n][0], plo[n][0]);
        bf2split(cS[n][2] * scB, cS[n][3] * scB, phi[n][1], plo[n][1]);
    }

    // ---- V now required: drain group B ----
    CP_WAIT0();
    __syncthreads();

    // ---- H = P V, fused 3-product HMMA loop; V via ldmatrix.x4.trans ----
    float cH[8][4];
    #pragma unroll
    for (int n = 0; n < 8; ++n)
        #pragma unroll
        for (int j = 0; j < 4; ++j) cH[n][j] = 0.f;

    #pragma unroll
    for (int kc = 0; kc < 8; ++kc) {
        uint32_t p0 = phi[2 * kc][0], p1 = phi[2 * kc][1];
        uint32_t p2 = phi[2 * kc + 1][0], p3 = phi[2 * kc + 1][1];
        uint32_t l0 = plo[2 * kc][0], l1 = plo[2 * kc][1];
        uint32_t l2 = plo[2 * kc + 1][0], l3 = plo[2 * kc + 1][1];
        uint32_t rowadr = vfrag + (uint32_t)kc * (16 * 272);
        #pragma unroll
        for (int np = 0; np < 4; ++np) {
            uint32_t vh0, vh1, vh2, vh3, vl0, vl1, vl2, vl3;
            LDM_X4T(vh0, vh1, vh2, vh3, rowadr + (uint32_t)np * 32);
            LDM_X4T(vl0, vl1, vl2, vl3, rowadr + 128 + (uint32_t)np * 32);
            mma16816(cH[2 * np],     p0, p1, p2, p3, vh0, vh1);
            mma16816(cH[2 * np + 1], p0, p1, p2, p3, vh2, vh3);
            mma16816(cH[2 * np],     p0, p1, p2, p3, vl0, vl1);
            mma16816(cH[2 * np + 1], p0, p1, p2, p3, vl2, vl3);
            mma16816(cH[2 * np],     l0, l1, l2, l3, vh0, vh1);
            mma16816(cH[2 * np + 1], l0, l1, l2, l3, vh2, vh3);
        }
    }

    // ---- epilogue: scatter-add ----
    {
        int nodeA = sNode[m0 + g];
        int nodeB = sNode[m0 + g + 8];
        float* dA = g_acc + (size_t)nodeA * 64;
        float* dB = g_acc + (size_t)nodeB * 64;
        #pragma unroll
        for (int n = 0; n < 8; ++n) {
            int col = 8 * n + 2 * t;
            atomicAdd(dA + col,     cH[n][0]);
            atomicAdd(dA + col + 1, cH[n][1]);
            atomicAdd(dB + col,     cH[n][2]);
            atomicAdd(dB + col + 1, cH[n][3]);
        }
        if (t == 0) {
            atomicAdd(&g_cnt[nodeA], 1.0f);
            atomicAdd(&g_cnt[nodeB], 1.0f);
        }
    }
}

// ---------------- projection + residual via HMMA (fused passes) ------------
#define PRJ_XHI 0
#define PRJ_XLO 18432
#define PRJ_WHI 36864
#define PRJ_WLO 46080
#define PRJ_SMEM 55296

__global__ void __launch_bounds__(256, 4) proj_kernel(
    const float* __restrict__ xv, const float* __restrict__ xc,
    const float* __restrict__ bout, float* __restrict__ out)
{
    extern __shared__ char sm[];
    __shared__ float sb[64];
    const int tid = threadIdx.x;
    const int wid = tid >> 5, lane = tid & 31;
    const int g = lane >> 2, t = lane & 3;
    const int m0 = wid * 16;
    const int r0 = blockIdx.x * 128;
    const uint32_t smu = smem_u32(sm);

    // async copy pre-split Wout (18432 B)
    for (int idx = tid; idx < 1152; idx += 256) {
        CP_ASYNC16(smu + PRJ_WHI + idx * 16,
                   (const char*)g_Wpre + 3 * 18432 + idx * 16);
    }
    CP_COMMIT();

    if (tid < 64) sb[tid] = bout[tid];

    {
        int row = tid >> 1, h32 = (tid & 1) * 32;
        int gr = r0 + row;
        char* xhi = sm + PRJ_XHI + row * 144 + h32 * 2;
        char* xlo = sm + PRJ_XLO + row * 144 + h32 * 2;
        if (gr < NTOT) {
            float rc = 1.0f / fmaxf(g_cnt[gr], 1.0f);
            const float* src = g_acc + (size_t)gr * 64 + h32;
            #pragma unroll
            for (int i = 0; i < 8; ++i) {
                float4 f = *(const float4*)(src + i * 4);
                uint32_t h0, l0, h1, l1;
                bf2split(f.x * rc, f.y * rc, h0, l0);
                bf2split(f.z * rc, f.w * rc, h1, l1);
                *(uint2*)(xhi + i * 8) = make_uint2(h0, h1);
                *(uint2*)(xlo + i * 8) = make_uint2(l0, l1);
            }
        } else {
            #pragma unroll
            for (int i = 0; i < 8; ++i) {
                *(uint64_t*)(xhi + i * 8) = 0ull;
                *(uint64_t*)(xlo + i * 8) = 0ull;
            }
        }
    }
    CP_WAIT0();
    __syncthreads();

    const int lrow = lane & 7;
    const uint32_t xfrag = smu +
        (uint32_t)(m0 + ((lane >> 3) & 1) * 8 + lrow) * 144 + (uint32_t)((lane >> 4) * 16);
    const uint32_t wfrag = smu + PRJ_WHI +
        (uint32_t)((lane >> 4) * 8 + lrow) * 144 + (uint32_t)(((lane >> 3) & 1) * 16);

    const int rA = r0 + m0 + g;
    const int rB = rA + 8;

    float c[8][4];
    #pragma unroll
    for (int n = 0; n < 8; ++n)
        #pragma unroll
        for (int j = 0; j < 4; ++j) c[n][j] = 0.f;

    #pragma unroll
    for (int kc = 0; kc < 4; ++kc) {
        uint32_t xh0, xh1, xh2, xh3, xl0, xl1, xl2, xl3;
        LDM_X4(xh0, xh1, xh2, xh3, xfrag + kc * 32);
        LDM_X4(xl0, xl1, xl2, xl3, xfrag + PRJ_XLO + kc * 32);
        #pragma unroll
        for (int nb = 0; nb < 4; ++nb) {
            uint32_t wh0, wh1, wh2, wh3, wl0, wl1, wl2, wl3;
            uint32_t wa = wfrag + (uint32_t)nb * 2304 + kc * 32;
            LDM_X4(wh0, wh1, wh2, wh3, wa);
            LDM_X4(wl0, wl1, wl2, wl3, wa + (PRJ_WLO - PRJ_WHI));
            mma16816(c[2 * nb],     xh0, xh1, xh2, xh3, wh0, wh1);
            mma16816(c[2 * nb + 1], xh0, xh1, xh2, xh3, wh2, wh3);
            mma16816(c[2 * nb],     xh0, xh1, xh2, xh3, wl0, wl1);
            mma16816(c[2 * nb + 1], xh0, xh1, xh2, xh3, wl2, wl3);
            mma16816(c[2 * nb],     xl0, xl1, xl2, xl3, wh0, wh1);
            mma16816(c[2 * nb + 1], xl0, xl1, xl2, xl3, wh2, wh3);
        }
    }

    if (rA < NTOT) {
        const float* xsrc = (rA < NV) ? xv + (size_t)rA * 64
                                      : xc + (size_t)(rA - NV) * 64;
        #pragma unroll
        for (int n = 0; n < 8; ++n) {
            int col = 8 * n + 2 * t;
            float2 xx = *(const float2*)(xsrc + col);
            float2 o;
            o.x = xx.x + sb[col] + c[n][0];
            o.y = xx.y + sb[col + 1] + c[n][1];
            *(float2*)(out + (size_t)rA * 64 + col) = o;
        }
    }
    if (rB < NTOT) {
        const float* xsrc = (rB < NV) ? xv + (size_t)rB * 64
                                      : xc + (size_t)(rB - NV) * 64;
        #pragma unroll
        for (int n = 0; n < 8; ++n) {
            int col = 8 * n + 2 * t;
            float2 xx = *(const float2*)(xsrc + col);
            float2 o;
            o.x = xx.x + sb[col] + c[n][2];
            o.y = xx.y + sb[col + 1] + c[n][3];
            *(float2*)(out + (size_t)rB * 64 + col) = o;
        }
    }
}

// ---------------- launcher -------------------------------------------------
extern "C" void kernel_launch(void* const* d_in, const int* in_sizes, int n_in,
                              void* d_out, int out_size)
{
    const float* xv   = (const float*)d_in[0];
    const float* xc   = (const float*)d_in[1];
    // d_in[2] edge_index, d_in[3] edge_polarity: unused by reference
    const int*   cvi  = (const int*)d_in[4];
    const int*   cci  = (const int*)d_in[5];
    const float* sat  = (const float*)d_in[6];
    const int*   ah   = (const int*)d_in[7];
    const float* WQ   = (const float*)d_in[8];
    const float* WK   = (const float*)d_in[9];
    const float* WV   = (const float*)d_in[10];
    const float* hw   = (const float*)d_in[11];
    const float* Wout = (const float*)d_in[12];
    const float* bout = (const float*)d_in[13];
    float* out = (float*)d_out;

    cudaFuncSetAttribute(qkv_kernel,  cudaFuncAttributeMaxDynamicSharedMemorySize, QKV_SMEM);
    cudaFuncSetAttribute(attn_kernel, cudaFuncAttributeMaxDynamicSharedMemorySize, ATTN_SMEM_BYTES);
    cudaFuncSetAttribute(proj_kernel, cudaFuncAttributeMaxDynamicSharedMemorySize, PRJ_SMEM);

    wprep_kernel<<<2, 256>>>(WQ, WK, WV, Wout);
    qkv_kernel<<<1563, 256, QKV_SMEM>>>(xv, xc);
    attn_kernel<<<CLUSTERS, 256, ATTN_SMEM_BYTES>>>(cvi, cci, sat, ah, hw);
    proj_kernel<<<1563, 256, PRJ_SMEM>>>(xv, xc, bout, out);
}

// round 16
// speedup vs baseline: 1.0386x; 1.0386x over previous
#include <cuda_runtime.h>
#include <cuda_bf16.h>
#include <cstdint>

#define NV 100000
#define NTOT 200000
#define CLUSTERS 2048
#define GAMMA 1.0f
#define NEG_SLOPE 0.2f

// ---------------- scratch (device globals; no allocation allowed) ----------
// per node: Qhi(64) Qlo(64) Khi(64) Klo(64) Vhi(64) Vlo(64) bf16 = 768 B
__device__ __align__(16) __nv_bfloat16 g_QKV[(size_t)NTOT * 384];
__device__ __align__(16) float g_acc[(size_t)NTOT * 64];
__device__ __align__(16) float g_cnt[NTOT];
// pre-split weights: 4 mats x [hi 64x144B | lo 64x144B] = 4 x 18432 B
__device__ __align__(16) char g_Wpre[73728];

// split float pair into (hi, lo) bf16x2 words; lower half = first element
__device__ __forceinline__ void bf2split(float a, float b, uint32_t& hi, uint32_t& lo) {
    __nv_bfloat162 h = __floats2bfloat162_rn(a, b);
    float ha = __bfloat162float(__low2bfloat16(h));
    float hb = __bfloat162float(__high2bfloat16(h));
    __nv_bfloat162 l = __floats2bfloat162_rn(a - ha, b - hb);
    hi = *reinterpret_cast<uint32_t*>(&h);
    lo = *reinterpret_cast<uint32_t*>(&l);
}

__device__ __forceinline__ void mma16816(float* c, uint32_t a0, uint32_t a1,
                                         uint32_t a2, uint32_t a3,
                                         uint32_t b0, uint32_t b1) {
    asm volatile(
        "mma.sync.aligned.m16n8k16.row.col.f32.bf16.bf16.f32 "
        "{%0,%1,%2,%3}, {%4,%5,%6,%7}, {%8,%9}, {%0,%1,%2,%3};"
        : "+f"(c[0]), "+f"(c[1]), "+f"(c[2]), "+f"(c[3])
        : "r"(a0), "r"(a1), "r"(a2), "r"(a3), "r"(b0), "r"(b1));
}

__device__ __forceinline__ uint32_t smem_u32(const void* p) {
    uint32_t a;
    asm("{ .reg .u64 t; cvta.to.shared.u64 t, %1; cvt.u32.u64 %0, t; }"
        : "=r"(a) : "l"(p));
    return a;
}

#define LDM_X4(r0_, r1_, r2_, r3_, addr) \
    asm volatile("ldmatrix.sync.aligned.m8n8.x4.shared.b16 {%0,%1,%2,%3}, [%4];" \
        : "=r"(r0_), "=r"(r1_), "=r"(r2_), "=r"(r3_) : "r"(addr))
#define LDM_X4T(r0_, r1_, r2_, r3_, addr) \
    asm volatile("ldmatrix.sync.aligned.m8n8.x4.trans.shared.b16 {%0,%1,%2,%3}, [%4];" \
        : "=r"(r0_), "=r"(r1_), "=r"(r2_), "=r"(r3_) : "r"(addr))

#define CP_ASYNC16(dst, src) \
    asm volatile("cp.async.cg.shared.global [%0], [%1], 16;" \
        :: "r"((uint32_t)(dst)), "l"(src) : "memory")
#define CP_COMMIT() asm volatile("cp.async.commit_group;" ::: "memory")
#define CP_WAIT0()  asm volatile("cp.async.wait_group 0;" ::: "memory")
#define CP_WAIT1()  asm volatile("cp.async.wait_group 1;" ::: "memory")

// ---------------- weight prep: split once into g_Wpre ----------------------
__global__ void __launch_bounds__(256) wprep_kernel(
    const float* __restrict__ WQ, const float* __restrict__ WK,
    const float* __restrict__ WV, const float* __restrict__ Wout)
{
    const float* Wsrc[4] = {WQ, WK, WV, Wout};
    int idx = blockIdx.x * 256 + threadIdx.x;     // 512 units total
    if (idx >= 512) return;
    int mat = idx >> 7;
    int rh  = idx & 127;
    int j = rh >> 1, h32 = (rh & 1) * 32;
    const float* w = Wsrc[mat] + j * 64 + h32;
    char* bhi = g_Wpre + mat * 18432 + j * 144 + h32 * 2;
    char* blo = bhi + 9216;
    #pragma unroll
    for (int i = 0; i < 8; ++i) {
        float4 f = *(const float4*)(w + i * 4);
        uint32_t h0, l0, h1, l1;
        bf2split(f.x, f.y, h0, l0);
        bf2split(f.z, f.w, h1, l1);
        *(uint2*)(bhi + i * 8) = make_uint2(h0, h1);
        *(uint2*)(blo + i * 8) = make_uint2(l0, l1);
    }
}

// ---------------- QKV via HMMA (128-row tiles, 3-pass, pre-split weights) --
#define QKV_XHI 0
#define QKV_XLO 18432
#define QKV_W   36864
#define QKV_SMEM 92160

__global__ void __launch_bounds__(256, 2) qkv_kernel(
    const float* __restrict__ xv, const float* __restrict__ xc)
{
    extern __shared__ char sm[];
    const int tid = threadIdx.x;
    const int wid = tid >> 5, lane = tid & 31;
    const int g = lane >> 2, t = lane & 3;
    const int m0 = wid * 16;
    const int r0 = blockIdx.x * 128;
    const uint32_t smu = smem_u32(sm);

    // ---- async copy of pre-split weights (55296 B) ----
    for (int idx = tid; idx < 3456; idx += 256) {
        CP_ASYNC16(smu + QKV_W + idx * 16, (const char*)g_Wpre + idx * 16);
    }
    CP_COMMIT();

    // ---- issue x-row loads early (MLP over the zero phase) ----
    const int xrow = tid >> 1, xh32 = (tid & 1) * 32;
    const int xgr = r0 + xrow;
    const bool xvalid = (xgr < NTOT);
    float4 xf[8];
    if (xvalid) {
        const float* src = (xgr < NV) ? xv + (size_t)xgr * 64 + xh32
                                      : xc + (size_t)(xgr - NV) * 64 + xh32;
        #pragma unroll
        for (int i = 0; i < 8; ++i) xf[i] = *(const float4*)(src + i * 4);
    }

    // ---- fused zero of g_acc / g_cnt ----
    {
        const size_t f4base = (size_t)r0 * 16;
        #pragma unroll
        for (int i = 0; i < 8; ++i) {
            size_t idx = f4base + tid + i * 256;
            if (idx < (size_t)NTOT * 16)
                ((float4*)g_acc)[idx] = make_float4(0.f, 0.f, 0.f, 0.f);
        }
        if (tid < 128 && r0 + tid < NTOT) g_cnt[r0 + tid] = 0.f;
    }

    // ---- convert + store x rows ----
    {
        char* xhi = sm + QKV_XHI + xrow * 144 + xh32 * 2;
        char* xlo = sm + QKV_XLO + xrow * 144 + xh32 * 2;
        if (xvalid) {
            #pragma unroll
            for (int i = 0; i < 8; ++i) {
                uint32_t h0, l0, h1, l1;
                bf2split(xf[i].x, xf[i].y, h0, l0);
                bf2split(xf[i].z, xf[i].w, h1, l1);
                *(uint2*)(xhi + i * 8) = make_uint2(h0, h1);
                *(uint2*)(xlo + i * 8) = make_uint2(l0, l1);
            }
        } else {
            #pragma unroll
            for (int i = 0; i < 8; ++i) {
                *(uint64_t*)(xhi + i * 8) = 0ull;
                *(uint64_t*)(xlo + i * 8) = 0ull;
            }
        }
    }
    CP_WAIT0();
    __syncthreads();

    const int lrow = lane & 7;
    const uint32_t xfrag = smu +
        (uint32_t)(m0 + ((lane >> 3) & 1) * 8 + lrow) * 144 + (uint32_t)((lane >> 4) * 16);
    const uint32_t wfrag = smu + QKV_W +
        (uint32_t)((lane >> 4) * 8 + lrow) * 144 + (uint32_t)(((lane >> 3) & 1) * 16);

    const int rA = r0 + m0 + g;
    const int rB = rA + 8;

    #pragma unroll 1
    for (int mat = 0; mat < 3; ++mat) {
        float c[8][4];
        #pragma unroll
        for (int n = 0; n < 8; ++n)
            #pragma unroll
            for (int j = 0; j < 4; ++j) c[n][j] = 0.f;

        #pragma unroll 1
        for (int pass = 0; pass < 3; ++pass) {
            uint32_t xb = xfrag + ((pass == 2) ? QKV_XLO : QKV_XHI);
            uint32_t wb = wfrag + (uint32_t)mat * 18432 + ((pass == 1) ? 9216u : 0u);
            #pragma unroll
            for (int kc = 0; kc < 4; ++kc) {
                uint32_t a0, a1, a2, a3;
                LDM_X4(a0, a1, a2, a3, xb + kc * 32);
                #pragma unroll
                for (int nb = 0; nb < 4; ++nb) {
                    uint32_t b0, b1, b2, b3;
                    LDM_X4(b0, b1, b2, b3, wb + (uint32_t)nb * 2304 + kc * 32);
                    mma16816(c[2 * nb],     a0, a1, a2, a3, b0, b1);
                    mma16816(c[2 * nb + 1], a0, a1, a2, a3, b2, b3);
                }
            }
        }

        if (rA < NTOT) {
            #pragma unroll
            for (int nn = 0; nn < 8; ++nn) {
                uint32_t hi, lo;
                bf2split(c[nn][0], c[nn][1], hi, lo);
                size_t off = (size_t)rA * 384 + mat * 128 + 8 * nn + 2 * t;
                *(uint32_t*)(g_QKV + off)      = hi;
                *(uint32_t*)(g_QKV + off + 64) = lo;
            }
        }
        if (rB < NTOT) {
            #pragma unroll
            for (int nn = 0; nn < 8; ++nn) {
                uint32_t hi, lo;
                bf2split(c[nn][2], c[nn][3], hi, lo);
                size_t off = (size_t)rB * 384 + mat * 128 + 8 * nn + 2 * t;
                *(uint32_t*)(g_QKV + off)      = hi;
                *(uint32_t*)(g_QKV + off + 64) = lo;
            }
        }
    }
}

// ---------------- HMMA attention (3-pass, two-group gather) ----------------
// smem: 3 tensors (Q, K, V), each [128 rows][272 B]: hi 128B | lo 128B | 16B pad
#define SQ 0
#define SK 34816
#define SV 69632
#define ATTN_SMEM_BYTES 104448

__global__ void __launch_bounds__(256) attn_kernel(
    const int* __restrict__ cvi, const int* __restrict__ cci,
    const float* __restrict__ sat, const int* __restrict__ active_heads,
    const float* __restrict__ head_weights)
{
    extern __shared__ char smc[];
    __shared__ int   sNode[128];
    __shared__ float sBias[128];
    __shared__ float sHw;

    const int tid  = threadIdx.x;
    const int wid  = tid >> 5;
    const int lane = tid & 31;
    const int c    = blockIdx.x;
    const int g    = lane >> 2;
    const int t    = lane & 3;
    const int m0   = wid * 16;
    const uint32_t smu = smem_u32(smc);

    if (tid < 64) {
        sNode[tid] = cvi[c * 64 + tid];
        sBias[tid] = 0.f;
    } else if (tid < 128) {
        int id = cci[c * 64 + tid - 64];
        sNode[tid] = NV + id;
        sBias[tid] = GAMMA * sat[id];
    }
    if (tid == 128) {
        int ah = active_heads[0];
        if (ah < 1) ah = 1;
        if (ah > 4) ah = 4;
        float s = 0.f;
        for (int h = 0; h < 4; ++h) if (h < ah) s += head_weights[h];
        sHw = s / (float)ah;
    }
    __syncthreads();

    // ---- gather via cp.async, two groups: [Q,K] then [V] ----
    {
        const int row = tid >> 1;
        const int h   = tid & 1;
        const int node = sNode[row];
        const char* src = (const char*)g_QKV + (size_t)node * 768;
        // group A: bytes 0..511 (Q hi/lo, K hi/lo)
        #pragma unroll
        for (int i = 0; i < 16; ++i) {
            int gb = (i * 2 + h) * 16;        // 0..496
            int part = gb >> 7;               // 0..3
            int tau = part >> 1;              // 0=Q,1=K
            int which = part & 1;
            int within = gb & 127;
            CP_ASYNC16(smu + tau * 34816 + row * 272 + which * 128 + within,
                       src + gb);
        }
        CP_COMMIT();
        // group B: bytes 512..767 (V hi/lo)
        #pragma unroll
        for (int i = 16; i < 24; ++i) {
            int gb = (i * 2 + h) * 16;        // 512..752
            int which = (gb >> 7) & 1;
            int within = gb & 127;
            CP_ASYNC16(smu + SV + row * 272 + which * 128 + within,
                       src + gb);
        }
        CP_COMMIT();
    }
    CP_WAIT1();        // Q,K resident; V still in flight
    __syncthreads();

    const int lrow = lane & 7;
    const uint32_t qfrag = smu + SQ +
        (uint32_t)(m0 + ((lane >> 3) & 1) * 8 + lrow) * 272 + (uint32_t)((lane >> 4) * 16);
    const uint32_t kfrag = smu + SK +
        (uint32_t)((lane >> 4) * 8 + lrow) * 272 + (uint32_t)(((lane >> 3) & 1) * 16);
    const uint32_t vfrag = smu + SV +
        (uint32_t)(((lane >> 3) & 1) * 8 + lrow) * 272 + (uint32_t)((lane >> 4) * 16);

    // ---- S = Q K^T via 3-pass bf16-split HMMA (ldmatrix operands) ----
    float cS[16][4];
    #pragma unroll
    for (int n = 0; n < 16; ++n)
        #pragma unroll
        for (int j = 0; j < 4; ++j) cS[n][j] = 0.f;

    #pragma unroll 1
    for (int pass = 0; pass < 3; ++pass) {
        uint32_t qb = qfrag + ((pass == 2) ? 128 : 0);
        uint32_t kb = kfrag + ((pass == 1) ? 128 : 0);
        #pragma unroll
        for (int kc = 0; kc < 4; ++kc) {
            uint32_t a0, a1, a2, a3;
            LDM_X4(a0, a1, a2, a3, qb + kc * 32);
            #pragma unroll
            for (int nb = 0; nb < 8; ++nb) {
                uint32_t b0, b1, b2, b3;
                LDM_X4(b0, b1, b2, b3, kb + (uint32_t)nb * (16 * 272) + kc * 32);
                mma16816(cS[2 * nb],     a0, a1, a2, a3, b0, b1);
                mma16816(cS[2 * nb + 1], a0, a1, a2, a3, b2, b3);
            }
        }
    }

    // ---- bias + leaky + softmax (register-resident) ----
    float mA = -1e30f, mB = -1e30f;
    #pragma unroll
    for (int n = 0; n < 16; ++n) {
        float b0v = sBias[8 * n + 2 * t];
        float b1v = sBias[8 * n + 2 * t + 1];
        float s;
        s = cS[n][0] * 0.125f + b0v; s = (s > 0.f) ? s : NEG_SLOPE * s; cS[n][0] = s; mA = fmaxf(mA, s);
        s = cS[n][1] * 0.125f + b1v; s = (s > 0.f) ? s : NEG_SLOPE * s; cS[n][1] = s; mA = fmaxf(mA, s);
        s = cS[n][2] * 0.125f + b0v; s = (s > 0.f) ? s : NEG_SLOPE * s; cS[n][2] = s; mB = fmaxf(mB, s);
        s = cS[n][3] * 0.125f + b1v; s = (s > 0.f) ? s : NEG_SLOPE * s; cS[n][3] = s; mB = fmaxf(mB, s);
    }
    mA = fmaxf(mA, __shfl_xor_sync(0xffffffffu, mA, 1));
    mA = fmaxf(mA, __shfl_xor_sync(0xffffffffu, mA, 2));
    mB = fmaxf(mB, __shfl_xor_sync(0xffffffffu, mB, 1));
    mB = fmaxf(mB, __shfl_xor_sync(0xffffffffu, mB, 2));

    float sA = 0.f, sB = 0.f;
    #pragma unroll
    for (int n = 0; n < 16; ++n) {
        cS[n][0] = __expf(cS[n][0] - mA); sA += cS[n][0];
        cS[n][1] = __expf(cS[n][1] - mA); sA += cS[n][1];
        cS[n][2] = __expf(cS[n][2] - mB); sB += cS[n][2];
        cS[n][3] = __expf(cS[n][3] - mB); sB += cS[n][3];
    }
    sA += __shfl_xor_sync(0xffffffffu, sA, 1);
    sA += __shfl_xor_sync(0xffffffffu, sA, 2);
    sB += __shfl_xor_sync(0xffffffffu, sB, 1);
    sB += __shfl_xor_sync(0xffffffffu, sB, 2);

    const float hw = sHw;
    const float scA = hw / sA;
    const float scB = hw / sB;

    uint32_t phi[16][2], plo[16][2];
    #pragma unroll
    for (int n = 0; n < 16; ++n) {
        bf2split(cS[n][0] * scA, cS[n][1] * scA, phi[n][0], plo[n][0]);
        bf2split(cS[n][2] * scB, cS[n][3] * scB, phi[n][1], plo[n][1]);
    }

    // ---- V now required: drain group B ----
    CP_WAIT0();
    __syncthreads();

    // ---- H = P V via 3-pass HMMA; V via ldmatrix.x4.trans ----
    float cH[8][4];
    #pragma unroll
    for (int n = 0; n < 8; ++n)
        #pragma unroll
        for (int j = 0; j < 4; ++j) cH[n][j] = 0.f;

    #pragma unroll 1
    for (int pass = 0; pass < 3; ++pass) {
        const uint32_t (*Pa)[2] = (pass == 2) ? plo : phi;
        const uint32_t voff = (pass == 1) ? 128u : 0u;
        #pragma unroll
        for (int kc = 0; kc < 8; ++kc) {
            uint32_t a0 = Pa[2 * kc][0];
            uint32_t a1 = Pa[2 * kc][1];
            uint32_t a2 = Pa[2 * kc + 1][0];
            uint32_t a3 = Pa[2 * kc + 1][1];
            uint32_t rowadr = vfrag + voff + (uint32_t)kc * (16 * 272);
            #pragma unroll
            for (int np = 0; np < 4; ++np) {
                uint32_t b0, b1, b2, b3;
                LDM_X4T(b0, b1, b2, b3, rowadr + (uint32_t)np * 32);
                mma16816(cH[2 * np],     a0, a1, a2, a3, b0, b1);
                mma16816(cH[2 * np + 1], a0, a1, a2, a3, b2, b3);
            }
        }
    }

    // ---- epilogue: scatter-add ----
    {
        int nodeA = sNode[m0 + g];
        int nodeB = sNode[m0 + g + 8];
        float* dA = g_acc + (size_t)nodeA * 64;
        float* dB = g_acc + (size_t)nodeB * 64;
        #pragma unroll
        for (int n = 0; n < 8; ++n) {
            int col = 8 * n + 2 * t;
            atomicAdd(dA + col,     cH[n][0]);
            atomicAdd(dA + col + 1, cH[n][1]);
            atomicAdd(dB + col,     cH[n][2]);
            atomicAdd(dB + col + 1, cH[n][3]);
        }
        if (t == 0) {
            atomicAdd(&g_cnt[nodeA], 1.0f);
            atomicAdd(&g_cnt[nodeB], 1.0f);
        }
    }
}

// ---------------- projection + residual via HMMA (fused passes) ------------
#define PRJ_XHI 0
#define PRJ_XLO 18432
#define PRJ_WHI 36864
#define PRJ_WLO 46080
#define PRJ_SMEM 55296

__global__ void __launch_bounds__(256, 4) proj_kernel(
    const float* __restrict__ xv, const float* __restrict__ xc,
    const float* __restrict__ bout, float* __restrict__ out)
{
    extern __shared__ char sm[];
    __shared__ float sb[64];
    const int tid = threadIdx.x;
    const int wid = tid >> 5, lane = tid & 31;
    const int g = lane >> 2, t = lane & 3;
    const int m0 = wid * 16;
    const int r0 = blockIdx.x * 128;
    const uint32_t smu = smem_u32(sm);

    // async copy pre-split Wout (18432 B)
    for (int idx = tid; idx < 1152; idx += 256) {
        CP_ASYNC16(smu + PRJ_WHI + idx * 16,
                   (const char*)g_Wpre + 3 * 18432 + idx * 16);
    }
    CP_COMMIT();

    if (tid < 64) sb[tid] = bout[tid];

    {
        int row = tid >> 1, h32 = (tid & 1) * 32;
        int gr = r0 + row;
        char* xhi = sm + PRJ_XHI + row * 144 + h32 * 2;
        char* xlo = sm + PRJ_XLO + row * 144 + h32 * 2;
        if (gr < NTOT) {
            float rc = 1.0f / fmaxf(g_cnt[gr], 1.0f);
            const float* src = g_acc + (size_t)gr * 64 + h32;
            #pragma unroll
            for (int i = 0; i < 8; ++i) {
                float4 f = *(const float4*)(src + i * 4);
                uint32_t h0, l0, h1, l1;
                bf2split(f.x * rc, f.y * rc, h0, l0);
                bf2split(f.z * rc, f.w * rc, h1, l1);
                *(uint2*)(xhi + i * 8) = make_uint2(h0, h1);
                *(uint2*)(xlo + i * 8) = make_uint2(l0, l1);
            }
        } else {
            #pragma unroll
            for (int i = 0; i < 8; ++i) {
                *(uint64_t*)(xhi + i * 8) = 0ull;
                *(uint64_t*)(xlo + i * 8) = 0ull;
            }
        }
    }
    CP_WAIT0();
    __syncthreads();

    const int lrow = lane & 7;
    const uint32_t xfrag = smu +
        (uint32_t)(m0 + ((lane >> 3) & 1) * 8 + lrow) * 144 + (uint32_t)((lane >> 4) * 16);
    const uint32_t wfrag = smu + PRJ_WHI +
        (uint32_t)((lane >> 4) * 8 + lrow) * 144 + (uint32_t)(((lane >> 3) & 1) * 16);

    const int rA = r0 + m0 + g;
    const int rB = rA + 8;

    float c[8][4];
    #pragma unroll
    for (int n = 0; n < 8; ++n)
        #pragma unroll
        for (int j = 0; j < 4; ++j) c[n][j] = 0.f;

    #pragma unroll
    for (int kc = 0; kc < 4; ++kc) {
        uint32_t xh0, xh1, xh2, xh3, xl0, xl1, xl2, xl3;
        LDM_X4(xh0, xh1, xh2, xh3, xfrag + kc * 32);
        LDM_X4(xl0, xl1, xl2, xl3, xfrag + PRJ_XLO + kc * 32);
        #pragma unroll
        for (int nb = 0; nb < 4; ++nb) {
            uint32_t wh0, wh1, wh2, wh3, wl0, wl1, wl2, wl3;
            uint32_t wa = wfrag + (uint32_t)nb * 2304 + kc * 32;
            LDM_X4(wh0, wh1, wh2, wh3, wa);
            LDM_X4(wl0, wl1, wl2, wl3, wa + (PRJ_WLO - PRJ_WHI));
            mma16816(c[2 * nb],     xh0, xh1, xh2, xh3, wh0, wh1);
            mma16816(c[2 * nb + 1], xh0, xh1, xh2, xh3, wh2, wh3);
            mma16816(c[2 * nb],     xh0, xh1, xh2, xh3, wl0, wl1);
            mma16816(c[2 * nb + 1], xh0, xh1, xh2, xh3, wl2, wl3);
            mma16816(c[2 * nb],     xl0, xl1, xl2, xl3, wh0, wh1);
            mma16816(c[2 * nb + 1], xl0, xl1, xl2, xl3, wh2, wh3);
        }
    }

    if (rA < NTOT) {
        const float* xsrc = (rA < NV) ? xv + (size_t)rA * 64
                                      : xc + (size_t)(rA - NV) * 64;
        #pragma unroll
        for (int n = 0; n < 8; ++n) {
            int col = 8 * n + 2 * t;
            float2 xx = *(const float2*)(xsrc + col);
            float2 o;
            o.x = xx.x + sb[col] + c[n][0];
            o.y = xx.y + sb[col + 1] + c[n][1];
            *(float2*)(out + (size_t)rA * 64 + col) = o;
        }
    }
    if (rB < NTOT) {
        const float* xsrc = (rB < NV) ? xv + (size_t)rB * 64
                                      : xc + (size_t)(rB - NV) * 64;
        #pragma unroll
        for (int n = 0; n < 8; ++n) {
            int col = 8 * n + 2 * t;
            float2 xx = *(const float2*)(xsrc + col);
            float2 o;
            o.x = xx.x + sb[col] + c[n][2];
            o.y = xx.y + sb[col + 1] + c[n][3];
            *(float2*)(out + (size_t)rB * 64 + col) = o;
        }
    }
}

// ---------------- launcher -------------------------------------------------
extern "C" void kernel_launch(void* const* d_in, const int* in_sizes, int n_in,
                              void* d_out, int out_size)
{
    const float* xv   = (const float*)d_in[0];
    const float* xc   = (const float*)d_in[1];
    // d_in[2] edge_index, d_in[3] edge_polarity: unused by reference
    const int*   cvi  = (const int*)d_in[4];
    const int*   cci  = (const int*)d_in[5];
    const float* sat  = (const float*)d_in[6];
    const int*   ah   = (const int*)d_in[7];
    const float* WQ   = (const float*)d_in[8];
    const float* WK   = (const float*)d_in[9];
    const float* WV   = (const float*)d_in[10];
    const float* hw   = (const float*)d_in[11];
    const float* Wout = (const float*)d_in[12];
    const float* bout = (const float*)d_in[13];
    float* out = (float*)d_out;

    cudaFuncSetAttribute(qkv_kernel,  cudaFuncAttributeMaxDynamicSharedMemorySize, QKV_SMEM);
    cudaFuncSetAttribute(attn_kernel, cudaFuncAttributeMaxDynamicSharedMemorySize, ATTN_SMEM_BYTES);
    cudaFuncSetAttribute(proj_kernel, cudaFuncAttributeMaxDynamicSharedMemorySize, PRJ_SMEM);

    wprep_kernel<<<2, 256>>>(WQ, WK, WV, Wout);
    qkv_kernel<<<1563, 256, QKV_SMEM>>>(xv, xc);
    attn_kernel<<<CLUSTERS, 256, ATTN_SMEM_BYTES>>>(cvi, cci, sat, ah, hw);
    proj_kernel<<<1563, 256, PRJ_SMEM>>>(xv, xc, bout, out);
}

// round 17
// speedup vs baseline: 1.0529x; 1.0137x over previous
#include <cuda_runtime.h>
#include <cuda_bf16.h>
#include <cstdint>

#define NV 100000
#define NTOT 200000
#define CLUSTERS 2048
#define GAMMA 1.0f
#define NEG_SLOPE 0.2f

// ---------------- scratch (device globals; no allocation allowed) ----------
// per node: Qhi(64) Qlo(64) Khi(64) Klo(64) Vhi(64) Vlo(64) bf16 = 768 B
__device__ __align__(16) __nv_bfloat16 g_QKV[(size_t)NTOT * 384];
__device__ __align__(16) float g_acc[(size_t)NTOT * 64];
__device__ __align__(16) float g_cnt[NTOT];
// pre-split weights: 4 mats x [hi 64x144B | lo 64x144B] = 4 x 18432 B
__device__ __align__(16) char g_Wpre[73728];

// split float pair into (hi, lo) bf16x2 words; lower half = first element
__device__ __forceinline__ void bf2split(float a, float b, uint32_t& hi, uint32_t& lo) {
    __nv_bfloat162 h = __floats2bfloat162_rn(a, b);
    float ha = __bfloat162float(__low2bfloat16(h));
    float hb = __bfloat162float(__high2bfloat16(h));
    __nv_bfloat162 l = __floats2bfloat162_rn(a - ha, b - hb);
    hi = *reinterpret_cast<uint32_t*>(&h);
    lo = *reinterpret_cast<uint32_t*>(&l);
}

__device__ __forceinline__ void mma16816(float* c, uint32_t a0, uint32_t a1,
                                         uint32_t a2, uint32_t a3,
                                         uint32_t b0, uint32_t b1) {
    asm volatile(
        "mma.sync.aligned.m16n8k16.row.col.f32.bf16.bf16.f32 "
        "{%0,%1,%2,%3}, {%4,%5,%6,%7}, {%8,%9}, {%0,%1,%2,%3};"
        : "+f"(c[0]), "+f"(c[1]), "+f"(c[2]), "+f"(c[3])
        : "r"(a0), "r"(a1), "r"(a2), "r"(a3), "r"(b0), "r"(b1));
}

__device__ __forceinline__ uint32_t smem_u32(const void* p) {
    uint32_t a;
    asm("{ .reg .u64 t; cvta.to.shared.u64 t, %1; cvt.u32.u64 %0, t; }"
        : "=r"(a) : "l"(p));
    return a;
}

#define LDM_X4(r0_, r1_, r2_, r3_, addr) \
    asm volatile("ldmatrix.sync.aligned.m8n8.x4.shared.b16 {%0,%1,%2,%3}, [%4];" \
        : "=r"(r0_), "=r"(r1_), "=r"(r2_), "=r"(r3_) : "r"(addr))
#define LDM_X4T(r0_, r1_, r2_, r3_, addr) \
    asm volatile("ldmatrix.sync.aligned.m8n8.x4.trans.shared.b16 {%0,%1,%2,%3}, [%4];" \
        : "=r"(r0_), "=r"(r1_), "=r"(r2_), "=r"(r3_) : "r"(addr))

#define CP_ASYNC16(dst, src) \
    asm volatile("cp.async.cg.shared.global [%0], [%1], 16;" \
        :: "r"((uint32_t)(dst)), "l"(src) : "memory")
#define CP_COMMIT() asm volatile("cp.async.commit_group;" ::: "memory")
#define CP_WAIT0()  asm volatile("cp.async.wait_group 0;" ::: "memory")
#define CP_WAIT1()  asm volatile("cp.async.wait_group 1;" ::: "memory")

#define RED_ADD2(ptr, a, b) \
    asm volatile("red.global.add.v2.f32 [%0], {%1, %2};" \
        :: "l"(ptr), "f"(a), "f"(b) : "memory")

// ---------------- weight prep: split once into g_Wpre ----------------------
__global__ void __launch_bounds__(256) wprep_kernel(
    const float* __restrict__ WQ, const float* __restrict__ WK,
    const float* __restrict__ WV, const float* __restrict__ Wout)
{
    const float* Wsrc[4] = {WQ, WK, WV, Wout};
    int idx = blockIdx.x * 256 + threadIdx.x;     // 512 units total
    if (idx >= 512) return;
    int mat = idx >> 7;
    int rh  = idx & 127;
    int j = rh >> 1, h32 = (rh & 1) * 32;
    const float* w = Wsrc[mat] + j * 64 + h32;
    char* bhi = g_Wpre + mat * 18432 + j * 144 + h32 * 2;
    char* blo = bhi + 9216;
    #pragma unroll
    for (int i = 0; i < 8; ++i) {
        float4 f = *(const float4*)(w + i * 4);
        uint32_t h0, l0, h1, l1;
        bf2split(f.x, f.y, h0, l0);
        bf2split(f.z, f.w, h1, l1);
        *(uint2*)(bhi + i * 8) = make_uint2(h0, h1);
        *(uint2*)(blo + i * 8) = make_uint2(l0, l1);
    }
}

// ---------------- QKV via HMMA (128-row tiles, 3-pass, pre-split weights) --
#define QKV_XHI 0
#define QKV_XLO 18432
#define QKV_W   36864
#define QKV_SMEM 92160

__global__ void __launch_bounds__(256, 2) qkv_kernel(
    const float* __restrict__ xv, const float* __restrict__ xc)
{
    extern __shared__ char sm[];
    const int tid = threadIdx.x;
    const int wid = tid >> 5, lane = tid & 31;
    const int g = lane >> 2, t = lane & 3;
    const int m0 = wid * 16;
    const int r0 = blockIdx.x * 128;
    const uint32_t smu = smem_u32(sm);

    // ---- async copy of pre-split weights (55296 B) ----
    for (int idx = tid; idx < 3456; idx += 256) {
        CP_ASYNC16(smu + QKV_W + idx * 16, (const char*)g_Wpre + idx * 16);
    }
    CP_COMMIT();

    // ---- issue x-row loads early (MLP over the zero phase) ----
    const int xrow = tid >> 1, xh32 = (tid & 1) * 32;
    const int xgr = r0 + xrow;
    const bool xvalid = (xgr < NTOT);
    float4 xf[8];
    if (xvalid) {
        const float* src = (xgr < NV) ? xv + (size_t)xgr * 64 + xh32
                                      : xc + (size_t)(xgr - NV) * 64 + xh32;
        #pragma unroll
        for (int i = 0; i < 8; ++i) xf[i] = *(const float4*)(src + i * 4);
    }

    // ---- fused zero of g_acc / g_cnt ----
    {
        const size_t f4base = (size_t)r0 * 16;
        #pragma unroll
        for (int i = 0; i < 8; ++i) {
            size_t idx = f4base + tid + i * 256;
            if (idx < (size_t)NTOT * 16)
                ((float4*)g_acc)[idx] = make_float4(0.f, 0.f, 0.f, 0.f);
        }
        if (tid < 128 && r0 + tid < NTOT) g_cnt[r0 + tid] = 0.f;
    }

    // ---- convert + store x rows ----
    {
        char* xhi = sm + QKV_XHI + xrow * 144 + xh32 * 2;
        char* xlo = sm + QKV_XLO + xrow * 144 + xh32 * 2;
        if (xvalid) {
            #pragma unroll
            for (int i = 0; i < 8; ++i) {
                uint32_t h0, l0, h1, l1;
                bf2split(xf[i].x, xf[i].y, h0, l0);
                bf2split(xf[i].z, xf[i].w, h1, l1);
                *(uint2*)(xhi + i * 8) = make_uint2(h0, h1);
                *(uint2*)(xlo + i * 8) = make_uint2(l0, l1);
            }
        } else {
            #pragma unroll
            for (int i = 0; i < 8; ++i) {
                *(uint64_t*)(xhi + i * 8) = 0ull;
                *(uint64_t*)(xlo + i * 8) = 0ull;
            }
        }
    }
    CP_WAIT0();
    __syncthreads();

    const int lrow = lane & 7;
    const uint32_t xfrag = smu +
        (uint32_t)(m0 + ((lane >> 3) & 1) * 8 + lrow) * 144 + (uint32_t)((lane >> 4) * 16);
    const uint32_t wfrag = smu + QKV_W +
        (uint32_t)((lane >> 4) * 8 + lrow) * 144 + (uint32_t)(((lane >> 3) & 1) * 16);

    const int rA = r0 + m0 + g;
    const int rB = rA + 8;

    #pragma unroll 1
    for (int mat = 0; mat < 3; ++mat) {
        float c[8][4];
        #pragma unroll
        for (int n = 0; n < 8; ++n)
            #pragma unroll
            for (int j = 0; j < 4; ++j) c[n][j] = 0.f;

        #pragma unroll 1
        for (int pass = 0; pass < 3; ++pass) {
            uint32_t xb = xfrag + ((pass == 2) ? QKV_XLO : QKV_XHI);
            uint32_t wb = wfrag + (uint32_t)mat * 18432 + ((pass == 1) ? 9216u : 0u);
            #pragma unroll
            for (int kc = 0; kc < 4; ++kc) {
                uint32_t a0, a1, a2, a3;
                LDM_X4(a0, a1, a2, a3, xb + kc * 32);
                #pragma unroll
                for (int nb = 0; nb < 4; ++nb) {
                    uint32_t b0, b1, b2, b3;
                    LDM_X4(b0, b1, b2, b3, wb + (uint32_t)nb * 2304 + kc * 32);
                    mma16816(c[2 * nb],     a0, a1, a2, a3, b0, b1);
                    mma16816(c[2 * nb + 1], a0, a1, a2, a3, b2, b3);
                }
            }
        }

        if (rA < NTOT) {
            #pragma unroll
            for (int nn = 0; nn < 8; ++nn) {
                uint32_t hi, lo;
                bf2split(c[nn][0], c[nn][1], hi, lo);
                size_t off = (size_t)rA * 384 + mat * 128 + 8 * nn + 2 * t;
                *(uint32_t*)(g_QKV + off)      = hi;
                *(uint32_t*)(g_QKV + off + 64) = lo;
            }
        }
        if (rB < NTOT) {
            #pragma unroll
            for (int nn = 0; nn < 8; ++nn) {
                uint32_t hi, lo;
                bf2split(c[nn][2], c[nn][3], hi, lo);
                size_t off = (size_t)rB * 384 + mat * 128 + 8 * nn + 2 * t;
                *(uint32_t*)(g_QKV + off)      = hi;
                *(uint32_t*)(g_QKV + off + 64) = lo;
            }
        }
    }
}

// ---------------- HMMA attention (3-pass, two-group gather) ----------------
// smem: 3 tensors (Q, K, V), each [128 rows][272 B]: hi 128B | lo 128B | 16B pad
#define SQ 0
#define SK 34816
#define SV 69632
#define ATTN_SMEM_BYTES 104448

__global__ void __launch_bounds__(256) attn_kernel(
    const int* __restrict__ cvi, const int* __restrict__ cci,
    const float* __restrict__ sat, const int* __restrict__ active_heads,
    const float* __restrict__ head_weights)
{
    extern __shared__ char smc[];
    __shared__ int   sNode[128];
    __shared__ float sBias[128];
    __shared__ float sHw;

    const int tid  = threadIdx.x;
    const int wid  = tid >> 5;
    const int lane = tid & 31;
    const int c    = blockIdx.x;
    const int g    = lane >> 2;
    const int t    = lane & 3;
    const int m0   = wid * 16;
    const uint32_t smu = smem_u32(smc);

    if (tid < 64) {
        sNode[tid] = cvi[c * 64 + tid];
        sBias[tid] = 0.f;
    } else if (tid < 128) {
        int id = cci[c * 64 + tid - 64];
        sNode[tid] = NV + id;
        sBias[tid] = GAMMA * sat[id];
    }
    if (tid == 128) {
        int ah = active_heads[0];
        if (ah < 1) ah = 1;
        if (ah > 4) ah = 4;
        float s = 0.f;
        for (int h = 0; h < 4; ++h) if (h < ah) s += head_weights[h];
        sHw = s / (float)ah;
    }
    __syncthreads();

    // ---- gather via cp.async, two groups: [Q,K] then [V] ----
    {
        const int row = tid >> 1;
        const int h   = tid & 1;
        const int node = sNode[row];
        const char* src = (const char*)g_QKV + (size_t)node * 768;
        // group A: bytes 0..511 (Q hi/lo, K hi/lo)
        #pragma unroll
        for (int i = 0; i < 16; ++i) {
            int gb = (i * 2 + h) * 16;        // 0..496
            int part = gb >> 7;               // 0..3
            int tau = part >> 1;              // 0=Q,1=K
            int which = part & 1;
            int within = gb & 127;
            CP_ASYNC16(smu + tau * 34816 + row * 272 + which * 128 + within,
                       src + gb);
        }
        CP_COMMIT();
        // group B: bytes 512..767 (V hi/lo)
        #pragma unroll
        for (int i = 16; i < 24; ++i) {
            int gb = (i * 2 + h) * 16;        // 512..752
            int which = (gb >> 7) & 1;
            int within = gb & 127;
            CP_ASYNC16(smu + SV + row * 272 + which * 128 + within,
                       src + gb);
        }
        CP_COMMIT();
    }
    CP_WAIT1();        // Q,K resident; V still in flight
    __syncthreads();

    const int lrow = lane & 7;
    const uint32_t qfrag = smu + SQ +
        (uint32_t)(m0 + ((lane >> 3) & 1) * 8 + lrow) * 272 + (uint32_t)((lane >> 4) * 16);
    const uint32_t kfrag = smu + SK +
        (uint32_t)((lane >> 4) * 8 + lrow) * 272 + (uint32_t)(((lane >> 3) & 1) * 16);
    const uint32_t vfrag = smu + SV +
        (uint32_t)(((lane >> 3) & 1) * 8 + lrow) * 272 + (uint32_t)((lane >> 4) * 16);

    // ---- S = Q K^T via 3-pass bf16-split HMMA (ldmatrix operands) ----
    float cS[16][4];
    #pragma unroll
    for (int n = 0; n < 16; ++n)
        #pragma unroll
        for (int j = 0; j < 4; ++j) cS[n][j] = 0.f;

    #pragma unroll 1
    for (int pass = 0; pass < 3; ++pass) {
        uint32_t qb = qfrag + ((pass == 2) ? 128 : 0);
        uint32_t kb = kfrag + ((pass == 1) ? 128 : 0);
        #pragma unroll
        for (int kc = 0; kc < 4; ++kc) {
            uint32_t a0, a1, a2, a3;
            LDM_X4(a0, a1, a2, a3, qb + kc * 32);
            #pragma unroll
            for (int nb = 0; nb < 8; ++nb) {
                uint32_t b0, b1, b2, b3;
                LDM_X4(b0, b1, b2, b3, kb + (uint32_t)nb * (16 * 272) + kc * 32);
                mma16816(cS[2 * nb],     a0, a1, a2, a3, b0, b1);
                mma16816(cS[2 * nb + 1], a0, a1, a2, a3, b2, b3);
            }
        }
    }

    // ---- bias + leaky + softmax (register-resident) ----
    float mA = -1e30f, mB = -1e30f;
    #pragma unroll
    for (int n = 0; n < 16; ++n) {
        float b0v = sBias[8 * n + 2 * t];
        float b1v = sBias[8 * n + 2 * t + 1];
        float s;
        s = cS[n][0] * 0.125f + b0v; s = (s > 0.f) ? s : NEG_SLOPE * s; cS[n][0] = s; mA = fmaxf(mA, s);
        s = cS[n][1] * 0.125f + b1v; s = (s > 0.f) ? s : NEG_SLOPE * s; cS[n][1] = s; mA = fmaxf(mA, s);
        s = cS[n][2] * 0.125f + b0v; s = (s > 0.f) ? s : NEG_SLOPE * s; cS[n][2] = s; mB = fmaxf(mB, s);
        s = cS[n][3] * 0.125f + b1v; s = (s > 0.f) ? s : NEG_SLOPE * s; cS[n][3] = s; mB = fmaxf(mB, s);
    }
    mA = fmaxf(mA, __shfl_xor_sync(0xffffffffu, mA, 1));
    mA = fmaxf(mA, __shfl_xor_sync(0xffffffffu, mA, 2));
    mB = fmaxf(mB, __shfl_xor_sync(0xffffffffu, mB, 1));
    mB = fmaxf(mB, __shfl_xor_sync(0xffffffffu, mB, 2));

    float sA = 0.f, sB = 0.f;
    #pragma unroll
    for (int n = 0; n < 16; ++n) {
        cS[n][0] = __expf(cS[n][0] - mA); sA += cS[n][0];
        cS[n][1] = __expf(cS[n][1] - mA); sA += cS[n][1];
        cS[n][2] = __expf(cS[n][2] - mB); sB += cS[n][2];
        cS[n][3] = __expf(cS[n][3] - mB); sB += cS[n][3];
    }
    sA += __shfl_xor_sync(0xffffffffu, sA, 1);
    sA += __shfl_xor_sync(0xffffffffu, sA, 2);
    sB += __shfl_xor_sync(0xffffffffu, sB, 1);
    sB += __shfl_xor_sync(0xffffffffu, sB, 2);

    const float hw = sHw;
    const float scA = hw / sA;
    const float scB = hw / sB;

    uint32_t phi[16][2], plo[16][2];
    #pragma unroll
    for (int n = 0; n < 16; ++n) {
        bf2split(cS[n][0] * scA, cS[n][1] * scA, phi[n][0], plo[n][0]);
        bf2split(cS[n][2] * scB, cS[n][3] * scB, phi[n][1], plo[n][1]);
    }

    // ---- V now required: drain group B ----
    CP_WAIT0();
    __syncthreads();

    // ---- H = P V via 3-pass HMMA; V via ldmatrix.x4.trans ----
    float cH[8][4];
    #pragma unroll
    for (int n = 0; n < 8; ++n)
        #pragma unroll
        for (int j = 0; j < 4; ++j) cH[n][j] = 0.f;

    #pragma unroll 1
    for (int pass = 0; pass < 3; ++pass) {
        const uint32_t (*Pa)[2] = (pass == 2) ? plo : phi;
        const uint32_t voff = (pass == 1) ? 128u : 0u;
        #pragma unroll
        for (int kc = 0; kc < 8; ++kc) {
            uint32_t a0 = Pa[2 * kc][0];
            uint32_t a1 = Pa[2 * kc][1];
            uint32_t a2 = Pa[2 * kc + 1][0];
            uint32_t a3 = Pa[2 * kc + 1][1];
            uint32_t rowadr = vfrag + voff + (uint32_t)kc * (16 * 272);
            #pragma unroll
            for (int np = 0; np < 4; ++np) {
                uint32_t b0, b1, b2, b3;
                LDM_X4T(b0, b1, b2, b3, rowadr + (uint32_t)np * 32);
                mma16816(cH[2 * np],     a0, a1, a2, a3, b0, b1);
                mma16816(cH[2 * np + 1], a0, a1, a2, a3, b2, b3);
            }
        }
    }

    // ---- epilogue: vectorized scatter-add (red.global.add.v2.f32) ----
    {
        int nodeA = sNode[m0 + g];
        int nodeB = sNode[m0 + g + 8];
        float* dA = g_acc + (size_t)nodeA * 64;
        float* dB = g_acc + (size_t)nodeB * 64;
        #pragma unroll
        for (int n = 0; n < 8; ++n) {
            int col = 8 * n + 2 * t;
            RED_ADD2(dA + col, cH[n][0], cH[n][1]);
            RED_ADD2(dB + col, cH[n][2], cH[n][3]);
        }
        if (t == 0) {
            atomicAdd(&g_cnt[nodeA], 1.0f);
            atomicAdd(&g_cnt[nodeB], 1.0f);
        }
    }
}

// ---------------- projection + residual via HMMA (fused passes) ------------
#define PRJ_XHI 0
#define PRJ_XLO 18432
#define PRJ_WHI 36864
#define PRJ_WLO 46080
#define PRJ_SMEM 55296

__global__ void __launch_bounds__(256, 4) proj_kernel(
    const float* __restrict__ xv, const float* __restrict__ xc,
    const float* __restrict__ bout, float* __restrict__ out)
{
    extern __shared__ char sm[];
    __shared__ float sb[64];
    const int tid = threadIdx.x;
    const int wid = tid >> 5, lane = tid & 31;
    const int g = lane >> 2, t = lane & 3;
    const int m0 = wid * 16;
    const int r0 = blockIdx.x * 128;
    const uint32_t smu = smem_u32(sm);

    // async copy pre-split Wout (18432 B)
    for (int idx = tid; idx < 1152; idx += 256) {
        CP_ASYNC16(smu + PRJ_WHI + idx * 16,
                   (const char*)g_Wpre + 3 * 18432 + idx * 16);
    }
    CP_COMMIT();

    if (tid < 64) sb[tid] = bout[tid];

    {
        int row = tid >> 1, h32 = (tid & 1) * 32;
        int gr = r0 + row;
        char* xhi = sm + PRJ_XHI + row * 144 + h32 * 2;
        char* xlo = sm + PRJ_XLO + row * 144 + h32 * 2;
        if (gr < NTOT) {
            float rc = 1.0f / fmaxf(g_cnt[gr], 1.0f);
            const float* src = g_acc + (size_t)gr * 64 + h32;
            #pragma unroll
            for (int i = 0; i < 8; ++i) {
                float4 f = *(const float4*)(src + i * 4);
                uint32_t h0, l0, h1, l1;
                bf2split(f.x * rc, f.y * rc, h0, l0);
                bf2split(f.z * rc, f.w * rc, h1, l1);
                *(uint2*)(xhi + i * 8) = make_uint2(h0, h1);
                *(uint2*)(xlo + i * 8) = make_uint2(l0, l1);
            }
        } else {
            #pragma unroll
            for (int i = 0; i < 8; ++i) {
                *(uint64_t*)(xhi + i * 8) = 0ull;
                *(uint64_t*)(xlo + i * 8) = 0ull;
            }
        }
    }
    CP_WAIT0();
    __syncthreads();

    const int lrow = lane & 7;
    const uint32_t xfrag = smu +
        (uint32_t)(m0 + ((lane >> 3) & 1) * 8 + lrow) * 144 + (uint32_t)((lane >> 4) * 16);
    const uint32_t wfrag = smu + PRJ_WHI +
        (uint32_t)((lane >> 4) * 8 + lrow) * 144 + (uint32_t)(((lane >> 3) & 1) * 16);

    const int rA = r0 + m0 + g;
    const int rB = rA + 8;

    float c[8][4];
    #pragma unroll
    for (int n = 0; n < 8; ++n)
        #pragma unroll
        for (int j = 0; j < 4; ++j) c[n][j] = 0.f;

    #pragma unroll
    for (int kc = 0; kc < 4; ++kc) {
        uint32_t xh0, xh1, xh2, xh3, xl0, xl1, xl2, xl3;
        LDM_X4(xh0, xh1, xh2, xh3, xfrag + kc * 32);
        LDM_X4(xl0, xl1, xl2, xl3, xfrag + PRJ_XLO + kc * 32);
        #pragma unroll
        for (int nb = 0; nb < 4; ++nb) {
            uint32_t wh0, wh1, wh2, wh3, wl0, wl1, wl2, wl3;
            uint32_t wa = wfrag + (uint32_t)nb * 2304 + kc * 32;
            LDM_X4(wh0, wh1, wh2, wh3, wa);
            LDM_X4(wl0, wl1, wl2, wl3, wa + (PRJ_WLO - PRJ_WHI));
            mma16816(c[2 * nb],     xh0, xh1, xh2, xh3, wh0, wh1);
            mma16816(c[2 * nb + 1], xh0, xh1, xh2, xh3, wh2, wh3);
            mma16816(c[2 * nb],     xh0, xh1, xh2, xh3, wl0, wl1);
            mma16816(c[2 * nb + 1], xh0, xh1, xh2, xh3, wl2, wl3);
            mma16816(c[2 * nb],     xl0, xl1, xl2, xl3, wh0, wh1);
            mma16816(c[2 * nb + 1], xl0, xl1, xl2, xl3, wh2, wh3);
        }
    }

    if (rA < NTOT) {
        const float* xsrc = (rA < NV) ? xv + (size_t)rA * 64
                                      : xc + (size_t)(rA - NV) * 64;
        #pragma unroll
        for (int n = 0; n < 8; ++n) {
            int col = 8 * n + 2 * t;
            float2 xx = *(const float2*)(xsrc + col);
            float2 o;
            o.x = xx.x + sb[col] + c[n][0];
            o.y = xx.y + sb[col + 1] + c[n][1];
            *(float2*)(out + (size_t)rA * 64 + col) = o;
        }
    }
    if (rB < NTOT) {
        const float* xsrc = (rB < NV) ? xv + (size_t)rB * 64
                                      : xc + (size_t)(rB - NV) * 64;
        #pragma unroll
        for (int n = 0; n < 8; ++n) {
            int col = 8 * n + 2 * t;
            float2 xx = *(const float2*)(xsrc + col);
            float2 o;
            o.x = xx.x + sb[col] + c[n][2];
            o.y = xx.y + sb[col + 1] + c[n][3];
            *(float2*)(out + (size_t)rB * 64 + col) = o;
        }
    }
}

// ---------------- launcher -------------------------------------------------
extern "C" void kernel_launch(void* const* d_in, const int* in_sizes, int n_in,
                              void* d_out, int out_size)
{
    const float* xv   = (const float*)d_in[0];
    const float* xc   = (const float*)d_in[1];
    // d_in[2] edge_index, d_in[3] edge_polarity: unused by reference
    const int*   cvi  = (const int*)d_in[4];
    const int*   cci  = (const int*)d_in[5];
    const float* sat  = (const float*)d_in[6];
    const int*   ah   = (const int*)d_in[7];
    const float* WQ   = (const float*)d_in[8];
    const float* WK   = (const float*)d_in[9];
    const float* WV   = (const float*)d_in[10];
    const float* hw   = (const float*)d_in[11];
    const float* Wout = (const float*)d_in[12];
    const float* bout = (const float*)d_in[13];
    float* out = (float*)d_out;

    cudaFuncSetAttribute(qkv_kernel,  cudaFuncAttributeMaxDynamicSharedMemorySize, QKV_SMEM);
    cudaFuncSetAttribute(attn_kernel, cudaFuncAttributeMaxDynamicSharedMemorySize, ATTN_SMEM_BYTES);
    cudaFuncSetAttribute(proj_kernel, cudaFuncAttributeMaxDynamicSharedMemorySize, PRJ_SMEM);

    wprep_kernel<<<2, 256>>>(WQ, WK, WV, Wout);
    qkv_kernel<<<1563, 256, QKV_SMEM>>>(xv, xc);
    attn_kernel<<<CLUSTERS, 256, ATTN_SMEM_BYTES>>>(cvi, cci, sat, ah, hw);
    proj_kernel<<<1563, 256, PRJ_SMEM>>>(xv, xc, bout, out);
}